// round 15
// baseline (speedup 1.0000x reference)
#include <cuda_runtime.h>
#include <cuda_fp16.h>
#include <stdint.h>
#include <math.h>

#define HIDDEN      512
#define BATCH       16384
#define NUM_LAYERS  8
#define NUM_OUTPUTS 16

#define BM 128
#define BN 128
#define BK 32                 // k per smem tile (32 fp16 = 64B per row)
#define KTILES (HIDDEN / BK)  // 16
#define THREADS 512           // 16 warps: 4 (M) x 4 (N), warp tile 32x32
#define STAGES 4              // power of 2 -> cheap buf index, extra reuse margin

#define ROWSTRIDE 80          // 64B data + 16B pad -> conflict-free ldmatrix
#define MAT_BYTES (128 * ROWSTRIDE)   // 10240 per matrix tile
#define NMATS 2               // x, w
#define BUF_BYTES (NMATS * MAT_BYTES) // 20480
#define OFF_BIAS  0
#define OFF_TILES 512
#define SMEM_TILES (OFF_TILES + STAGES * BUF_BYTES)     // 82432
#define SMEM_STAGE (OFF_TILES + 128 * 132 * 4)          // 68096 (bcast epilogue)
#define SMEM_ALLOC (SMEM_STAGE > SMEM_TILES ? SMEM_STAGE : SMEM_TILES)

#define WSCALE 4.419417382415922e-4f   // 0.01 / sqrt(512)
#define BSCALE 0.01f
#define GAIN   1.4142135623730951f
#define SLOPE  0.2f

// Device-global scratch (allocation-free): fp16 activations + fp16 weights
__device__ __align__(16) __half g_xA[BATCH * HIDDEN];
__device__ __align__(16) __half g_xB[BATCH * HIDDEN];
__device__ __align__(16) __half g_wh[NUM_LAYERS * HIDDEN * HIDDEN];

// ---------------------------------------------------------------------------
__device__ __forceinline__ uint32_t smem_u32(const void* p) {
    uint32_t a;
    asm("{ .reg .u64 t; cvta.to.shared.u64 t, %1; cvt.u32.u64 %0, t; }"
        : "=r"(a) : "l"(p));
    return a;
}
// pack two fp32 -> fp16x2 (a in low half)
__device__ __forceinline__ uint32_t pack_h2(float a, float b) {
    uint32_t r;
    asm("cvt.rn.f16x2.f32 %0, %1, %2;" : "=r"(r) : "f"(b), "f"(a));
    return r;
}
__device__ __forceinline__ float lrelu_gain(float t) {
    return (t > 0.f ? t : SLOPE * t) * GAIN;
}

#define CP_ASYNC16(dst, src) \
    asm volatile("cp.async.cg.shared.global [%0], [%1], 16;" :: "r"(dst), "l"(src))
#define CP_COMMIT() asm volatile("cp.async.commit_group;" ::: "memory")
#define CP_WAITG(n) asm volatile("cp.async.wait_group %0;" :: "n"(n) : "memory")

#define LDSM_X4(r0, r1, r2, r3, addr) \
    asm volatile("ldmatrix.sync.aligned.m8n8.x4.shared.b16 {%0,%1,%2,%3}, [%4];" \
                 : "=r"(r0), "=r"(r1), "=r"(r2), "=r"(r3) : "r"(addr))

#define MMA16816H(c, a, b0, b1) \
    asm volatile("mma.sync.aligned.m16n8k16.row.col.f32.f16.f16.f32 " \
                 "{%0,%1,%2,%3}, {%4,%5,%6,%7}, {%8,%9}, {%0,%1,%2,%3};" \
                 : "+f"((c)[0]), "+f"((c)[1]), "+f"((c)[2]), "+f"((c)[3]) \
                 : "r"((a)[0]), "r"((a)[1]), "r"((a)[2]), "r"((a)[3]), \
                   "r"(b0), "r"(b1))

// ---------------------------------------------------------------------------
// Convert all layer weights to raw fp16 (wscale applied in GEMM epilogue)
// ---------------------------------------------------------------------------
__global__ void conv_w_kernel(const float* __restrict__ W,
                              __half* __restrict__ wh) {
    int base = (blockIdx.x * blockDim.x + threadIdx.x) * 4;
    float4 w = *reinterpret_cast<const float4*>(W + base);
    *reinterpret_cast<uint2*>(&wh[base]) =
        make_uint2(pack_h2(w.x, w.y), pack_h2(w.z, w.w));
}

// ---------------------------------------------------------------------------
// Pixel norm -> fp16 activations
// ---------------------------------------------------------------------------
__global__ void pixelnorm_kernel(const float* __restrict__ z,
                                 __half* __restrict__ x) {
    int row  = blockIdx.x * blockDim.y + threadIdx.y;
    int lane = threadIdx.x;
    const float4* zr = reinterpret_cast<const float4*>(z + (size_t)row * HIDDEN);
    float4 v[4];
    float ss = 0.f;
#pragma unroll
    for (int i = 0; i < 4; i++) {
        v[i] = zr[lane + 32 * i];
        ss += v[i].x * v[i].x + v[i].y * v[i].y + v[i].z * v[i].z + v[i].w * v[i].w;
    }
#pragma unroll
    for (int off = 16; off > 0; off >>= 1)
        ss += __shfl_xor_sync(0xFFFFFFFFu, ss, off);
    float s = rsqrtf(ss * (1.0f / HIDDEN) + 1e-8f);
#pragma unroll
    for (int i = 0; i < 4; i++) {
        int e = row * HIDDEN + (lane + 32 * i) * 4;
        *reinterpret_cast<uint2*>(&x[e]) =
            make_uint2(pack_h2(v[i].x * s, v[i].y * s),
                       pack_h2(v[i].z * s, v[i].w * s));
    }
}

// ---------------------------------------------------------------------------
// HMMA dense layer: acc = X @ Wraw^T (fp16 in, fp32 accum, 1 MMA term)
// Y = lrelu(acc*wscale + b*bscale)*sqrt(2) -> fp16 (or fp32 broadcast).
// 16 warps (4Mx4N), warp tile 32x32, BK=32, 4-stage cp.async ring,
// double-buffered register fragments, mainloop fully unrolled.
// ---------------------------------------------------------------------------
template <bool BROADCAST>
__global__ __launch_bounds__(THREADS, 1)
void dense_mma(const __half* __restrict__ X,
               const __half* __restrict__ Wh,
               const float* __restrict__ Bv,
               __half* __restrict__ Y,
               float* __restrict__ Yout) {
    extern __shared__ char smem[];
    const uint32_t sbase = smem_u32(smem);
    float* bias_s = reinterpret_cast<float*>(smem + OFF_BIAS);

    const int tid  = threadIdx.x;
    const int wid  = tid >> 5;
    const int lane = tid & 31;
    const int mBase = blockIdx.y * BM;
    const int nBase = blockIdx.x * BN;
    const int wmBase = (wid & 3) * 32;   // warp M offset
    const int wnBase = (wid >> 2) * 32;  // warp N offset

    if (tid < BN) bias_s[tid] = Bv[nBase + tid] * BSCALE;

    // hoisted per-thread global sources (advance kt*BK under unroll)
    const int ld_row = tid >> 2;                 // 0..127
    const int ld_c   = tid & 3;                  // 16B chunk in 64B row
    const __half* gx = X  + (size_t)(mBase + ld_row) * HIDDEN + ld_c * 8;
    const __half* gw = Wh + (size_t)(nBase + ld_row) * HIDDEN + ld_c * 8;
    const uint32_t ld_soff =
        (uint32_t)(ld_row * ROWSTRIDE + ld_c * 16) + sbase + OFF_TILES;

    auto load_tile = [&](int kt, int buf) {
        uint32_t dst = ld_soff + buf * BUF_BYTES;
        CP_ASYNC16(dst, gx + kt * BK);
        CP_ASYNC16(dst + MAT_BYTES, gw + kt * BK);
    };

    // per-warp ldsm address components (constant across steps)
    const uint32_t a_off0 = sbase + OFF_TILES +
        (uint32_t)((wmBase + (lane & 15)) * ROWSTRIDE + (lane >> 4) * 16);
    const int bg = lane >> 3, br = lane & 7;
    const uint32_t b_off0 = sbase + OFF_TILES + MAT_BYTES +
        (uint32_t)((wnBase + (bg >> 1) * 8 + br) * ROWSTRIDE + (bg & 1) * 16);

    auto load_frags = [&](int buf, int s, uint32_t aF[2][4], uint32_t bW[4][2]) {
        const uint32_t bo = buf * BUF_BYTES + (uint32_t)(2 * s * 16);
#pragma unroll
        for (int mi = 0; mi < 2; mi++) {
            uint32_t ad = a_off0 + bo + mi * 16 * ROWSTRIDE;
            LDSM_X4(aF[mi][0], aF[mi][1], aF[mi][2], aF[mi][3], ad);
        }
#pragma unroll
        for (int p = 0; p < 2; p++) {
            uint32_t bd = b_off0 + bo + p * 16 * ROWSTRIDE;
            LDSM_X4(bW[2 * p][0], bW[2 * p][1], bW[2 * p + 1][0],
                    bW[2 * p + 1][1], bd);
        }
    };

    float c[2][4][4];
#pragma unroll
    for (int mi = 0; mi < 2; mi++)
#pragma unroll
        for (int ni = 0; ni < 4; ni++)
#pragma unroll
            for (int j = 0; j < 4; j++) c[mi][ni][j] = 0.f;

    auto do_mma = [&](uint32_t aF[2][4], uint32_t bW[4][2]) {
#pragma unroll
        for (int mi = 0; mi < 2; mi++)
#pragma unroll
            for (int ni = 0; ni < 4; ni++)
                MMA16816H(c[mi][ni], aF[mi], bW[ni][0], bW[ni][1]);
    };

    uint32_t aF[2][2][4], bW[2][4][2];

    load_tile(0, 0); CP_COMMIT();
    load_tile(1, 1); CP_COMMIT();
    CP_WAITG(1);            // tile 0 resident
    __syncthreads();
    load_frags(0, 0, aF[0], bW[0]);

#pragma unroll
    for (int kt = 0; kt < KTILES; kt++) {
        const int buf = kt & (STAGES - 1);

        // LDSMs for step 1 issue before MMAs of step 0 -> latency hidden
        load_frags(buf, 1, aF[1], bW[1]);
        do_mma(aF[0], bW[0]);

        if (kt + 2 < KTILES) {          // prefetch tile kt+2 (ring has room)
            load_tile(kt + 2, (kt + 2) & (STAGES - 1));
            CP_COMMIT();
        }
        if (kt + 1 < KTILES) {
            if (kt + 2 < KTILES) CP_WAITG(1); else CP_WAITG(0);  // tile kt+1 in
            __syncthreads();            // all warps done reading tile kt-ish
            load_frags((kt + 1) & (STAGES - 1), 0, aF[0], bW[0]);
        }
        do_mma(aF[1], bW[1]);
    }

    // ---- epilogue ----
    if (BROADCAST) {
        // stage fp32 tile in smem (reuse tile buffers), then coalesced float4
        __syncthreads();
        float* stage = reinterpret_cast<float*>(smem + OFF_TILES);
        const int LDSTG = 132;   // padded fp32 row stride
#pragma unroll
        for (int mi = 0; mi < 2; mi++) {
            int r0 = wmBase + mi * 16 + (lane >> 2);
#pragma unroll
            for (int ni = 0; ni < 4; ni++) {
                int n = wnBase + ni * 8 + (lane & 3) * 2;
                stage[r0 * LDSTG + n] =
                    lrelu_gain(c[mi][ni][0] * WSCALE + bias_s[n]);
                stage[r0 * LDSTG + n + 1] =
                    lrelu_gain(c[mi][ni][1] * WSCALE + bias_s[n + 1]);
                stage[(r0 + 8) * LDSTG + n] =
                    lrelu_gain(c[mi][ni][2] * WSCALE + bias_s[n]);
                stage[(r0 + 8) * LDSTG + n + 1] =
                    lrelu_gain(c[mi][ni][3] * WSCALE + bias_s[n + 1]);
            }
        }
        __syncthreads();
        // 128 rows x 16 reps x 32 float4-cols, 512 threads -> 128 iters
        for (int it = tid; it < 128 * NUM_OUTPUTS * 32; it += THREADS) {
            int col4 = it & 31;
            int rep  = (it >> 5) & 15;
            int row  = it >> 9;
            float4 v = *reinterpret_cast<const float4*>(
                &stage[row * LDSTG + col4 * 4]);
            *reinterpret_cast<float4*>(
                Yout + ((size_t)(mBase + row) * NUM_OUTPUTS + rep) * HIDDEN
                     + nBase + col4 * 4) = v;
        }
    } else {
#pragma unroll
        for (int mi = 0; mi < 2; mi++) {
            int m0 = mBase + wmBase + mi * 16 + (lane >> 2);
#pragma unroll
            for (int ni = 0; ni < 4; ni++) {
                int n = nBase + wnBase + ni * 8 + (lane & 3) * 2;
                float v0 = lrelu_gain(c[mi][ni][0] * WSCALE + bias_s[n - nBase]);
                float v1 = lrelu_gain(c[mi][ni][1] * WSCALE + bias_s[n - nBase + 1]);
                float v2 = lrelu_gain(c[mi][ni][2] * WSCALE + bias_s[n - nBase]);
                float v3 = lrelu_gain(c[mi][ni][3] * WSCALE + bias_s[n - nBase + 1]);
                size_t e0 = (size_t)m0 * HIDDEN + n;
                size_t e1 = e0 + (size_t)8 * HIDDEN;
                *reinterpret_cast<uint32_t*>(&Y[e0]) = pack_h2(v0, v1);
                *reinterpret_cast<uint32_t*>(&Y[e1]) = pack_h2(v2, v3);
            }
        }
    }
}

// ---------------------------------------------------------------------------
extern "C" void kernel_launch(void* const* d_in, const int* in_sizes, int n_in,
                              void* d_out, int out_size) {
    const float* z      = (const float*)d_in[0];
    const float* weight = (const float*)d_in[1];
    const float* bias   = (const float*)d_in[2];
    float* out          = (float*)d_out;

    __half *xA, *xB, *wh;
    cudaGetSymbolAddress((void**)&xA, g_xA);
    cudaGetSymbolAddress((void**)&xB, g_xB);
    cudaGetSymbolAddress((void**)&wh, g_wh);

    cudaFuncSetAttribute(dense_mma<false>,
                         cudaFuncAttributeMaxDynamicSharedMemorySize, SMEM_ALLOC);
    cudaFuncSetAttribute(dense_mma<true>,
                         cudaFuncAttributeMaxDynamicSharedMemorySize, SMEM_ALLOC);

    // 1) convert all weights to raw fp16 (wscale folded into epilogue)
    conv_w_kernel<<<NUM_LAYERS * HIDDEN * HIDDEN / (256 * 4), 256>>>(weight, wh);

    // 2) pixel norm -> fp16 activations (buffer A)
    pixelnorm_kernel<<<BATCH / 8, dim3(32, 8)>>>(z, xA);

    // 3) 8 HMMA dense layers, ping-pong; last broadcasts into wp
    dim3 grid(HIDDEN / BN, BATCH / BM);  // (4, 128)
    for (int l = 0; l < NUM_LAYERS; l++) {
        const __half* Wl = wh + (size_t)l * HIDDEN * HIDDEN;
        const float* Bl = bias + (size_t)l * HIDDEN;
        const __half* src = (l & 1) ? xB : xA;
        __half* dst       = (l & 1) ? xA : xB;
        if (l == NUM_LAYERS - 1) {
            dense_mma<true><<<grid, THREADS, SMEM_ALLOC>>>(
                src, Wl, Bl, nullptr, out);
        } else {
            dense_mma<false><<<grid, THREADS, SMEM_ALLOC>>>(
                src, Wl, Bl, dst, nullptr);
        }
    }
}